// round 16
// baseline (speedup 1.0000x reference)
#include <cuda_runtime.h>
#include <cuda_bf16.h>
#include <math.h>
#include <stdint.h>

// Problem constants: B=8, T=512, N=128, F=16, H=32, L=4
#define BTNH_ 16777216ull   // floats per layer of tcn
#define TCN_L2 8388608ull   // float2 per layer of tcn

// Scratch (allocation-free: static device globals)
// tcn in k_layers D-frag order: float2[(bt*8+g)*8 + nt*2+rg][lane] per layer
__device__ float g_tcn[4ull * 16777216ull];
// Precomputed constant fragments (filled by k_prep each launch)
__device__ uint32_t g_afragH[8192];  // A frags: [mt8][ks8][lane32][4]
__device__ uint32_t g_afragL[8192];
__device__ uint32_t g_wH32[6912];    // gemm wts: 12x512 + out1@6144 + out2@6656
__device__ uint32_t g_wL32[6912];
__device__ uint32_t g_cwH[8192];     // conv wts: [(l*2+conv)]x1024
__device__ uint32_t g_cwL[8192];

// ====================== common helpers ======================
__device__ __forceinline__ uint32_t smem_u32(const void* p) {
    uint32_t a;
    asm("{ .reg .u64 t; cvta.to.shared.u64 t, %1; cvt.u32.u64 %0, t; }"
        : "=r"(a) : "l"(p));
    return a;
}
__device__ __forceinline__ void ldmat4(uint32_t r[4], uint32_t addr) {
    asm volatile("ldmatrix.sync.aligned.m8n8.x4.shared.b16 {%0,%1,%2,%3}, [%4];"
                 : "=r"(r[0]), "=r"(r[1]), "=r"(r[2]), "=r"(r[3]) : "r"(addr));
}
__device__ __forceinline__ void mma16816(float d[4], const uint32_t a[4],
                                         uint32_t b0, uint32_t b1) {
    asm volatile(
        "mma.sync.aligned.m16n8k16.row.col.f32.bf16.bf16.f32 "
        "{%0,%1,%2,%3}, {%4,%5,%6,%7}, {%8,%9}, {%0,%1,%2,%3};"
        : "+f"(d[0]), "+f"(d[1]), "+f"(d[2]), "+f"(d[3])
        : "r"(a[0]), "r"(a[1]), "r"(a[2]), "r"(a[3]), "r"(b0), "r"(b1));
}
__device__ __forceinline__ uint32_t pack_bf16(__nv_bfloat16 lo, __nv_bfloat16 hi) {
    return (uint32_t)__bfloat16_as_ushort(lo) |
           ((uint32_t)__bfloat16_as_ushort(hi) << 16);
}
__device__ __forceinline__ void split2(float v0, float v1, uint32_t& hw,
                                       uint32_t& lw) {
    __nv_bfloat16 h0 = __float2bfloat16(v0), h1 = __float2bfloat16(v1);
    hw = pack_bf16(h0, h1);
    lw = pack_bf16(__float2bfloat16(v0 - __bfloat162float(h0)),
                   __float2bfloat16(v1 - __bfloat162float(h1)));
}

// ---------------------------------------------------------------------------
// K0: fragment prep — A frags, gemm-weight frags, conv-weight frags.
// ---------------------------------------------------------------------------
__global__ void k_prep(const float* __restrict__ A,
                       const float* __restrict__ gcn_w,
                       const float* __restrict__ skip_w,
                       const float* __restrict__ res_w,
                       const float* __restrict__ out1_w,
                       const float* __restrict__ out2_w,
                       const float* __restrict__ ct_w,
                       const float* __restrict__ cs_w) {
    int tid = blockIdx.x * blockDim.x + threadIdx.x;
    int nthr = gridDim.x * blockDim.x;

    // A frags: m16n8k16 A-operand layout, 8 mtiles x 8 ks x 32 lanes x 4 words
    for (int idx = tid; idx < 2048; idx += nthr) {
        int mt = idx >> 8, ks = (idx >> 5) & 7, lane = idx & 31;
        int r = lane >> 2, c = lane & 3;
        int row = mt * 16 + r, k = ks * 16 + 2 * c;
        uint32_t base = (uint32_t)idx * 4;
#pragma unroll
        for (int j = 0; j < 4; j++) {
            int rr = row + (j & 1) * 8;
            int kk = k + (j >> 1) * 8;
            uint32_t hw, lw;
            split2(A[rr * 128 + kk], A[rr * 128 + kk + 1], hw, lw);
            g_afragH[base + j] = hw;
            g_afragL[base + j] = lw;
        }
    }
    // gemm weights: 13 matrices x 512 words (lane-keyed frag layout)
    for (int idx = tid; idx < 6656; idx += nthr) {
        int m = idx >> 9, i = idx & 511;
        const float* W;
        if (m == 12) W = out1_w;
        else {
            int l = m / 3, kind = m % 3;
            W = (kind == 0 ? gcn_w : kind == 1 ? skip_w : res_w) + l * 1024;
        }
        int cp = i >> 5, o = i & 31;
        uint32_t hw, lw;
        split2(W[(2 * cp) * 32 + o], W[(2 * cp + 1) * 32 + o], hw, lw);
        int kc = cp >> 3, r = cp & 7;
        int e = (kc * 4 + (o >> 3)) * 32 + (((o & 7) << 2) | (r & 3));
        int slot = m * 512 + e * 2 + (r >> 2);
        g_wH32[slot] = hw;
        g_wL32[slot] = lw;
    }
    // out2: 256 words at offset 6656
    for (int idx = tid; idx < 256; idx += nthr) {
        int cp = idx >> 4, o = idx & 15;
        uint32_t hw, lw;
        split2(out2_w[(2 * cp) * 16 + o], out2_w[(2 * cp + 1) * 16 + o], hw, lw);
        int kc = cp >> 3, r = cp & 7;
        int e = (kc * 2 + (o >> 3)) * 32 + (((o & 7) << 2) | (r & 3));
        g_wH32[6656 + e * 2 + (r >> 2)] = hw;
        g_wL32[6656 + e * 2 + (r >> 2)] = lw;
    }
    // conv weights: 8 matrices (l*2+conv) x 1024 words
    for (int idx = tid; idx < 8192; idx += nthr) {
        int cv = idx >> 10, i = idx & 1023;
        int l = cv >> 1;
        const float* W = ((cv & 1) ? cs_w : ct_w) + l * 2048;
        int krow = i >> 5, o = i & 31;
        int k0 = krow * 2;
        const float* src = W + (k0 >> 5) * 1024 + (k0 & 31) * 32 + o;
        uint32_t hw, lw;
        split2(src[0], src[32], hw, lw);
        int ks = krow >> 3, r = krow & 7;
        int e = (ks * 4 + (o >> 3)) * 32 + (((o & 7) << 2) | (r & 3));
        int slot = cv * 1024 + e * 2 + (r >> 2);
        g_cwH[slot] = hw;
        g_cwL[slot] = lw;
    }
}

// ---------------------------------------------------------------------------
// K2: fused input-proj (x_a/x_b) + gated dilated causal convs (HMMA).
// Gate = copysign(1-t, a) * rcp((1+t)(1+u)): one MUFU.RCP per value.
// tcn written directly in k_layers' D-frag order.
// ---------------------------------------------------------------------------
#define XAH_B 0
#define XAL_B 41600
#define XBH_B 83200
#define XBL_B 124800
#define K2_SMEM 166400
// proj temp (inside XBL region, 41600 B available)
#define TXI_B XBL_B            // 512*17 floats = 34816 B
#define TWI_B (XBL_B + 34816)  // 16*64 floats  = 4096 B
#define TBI_B (XBL_B + 38912)  // 64 floats     = 256 B

__device__ __forceinline__ void conv_mma(uint32_t sbase,
                                         uint32_t xh, uint32_t xl,
                                         const uint2* __restrict__ wH2,
                                         const uint2* __restrict__ wL2,
                                         const float* __restrict__ bias,
                                         int tau0w, int lane, int d,
                                         float acc[2][4][4]) {
#pragma unroll
    for (int nt = 0; nt < 4; nt++) {
        float2 bv = __ldg((const float2*)(bias + nt * 8 + (lane & 3) * 2));
#pragma unroll
        for (int mt = 0; mt < 2; mt++) {
            acc[mt][nt][0] = bv.x; acc[mt][nt][1] = bv.y;
            acc[mt][nt][2] = bv.x; acc[mt][nt][3] = bv.y;
        }
    }
    int rbase = 8 + tau0w + (lane & 15);
    int chan = (lane >> 4) * 8;
#pragma unroll
    for (int ks = 0; ks < 4; ks++) {
        int tsh = (ks < 2) ? d : 0;
        int ch = chan + (ks & 1) * 16;
        uint32_t arow = (uint32_t)((rbase - tsh) * 80 + ch * 2);
        uint32_t ah[2][4], al[2][4];
        ldmat4(ah[0], sbase + xh + arow);
        ldmat4(ah[1], sbase + xh + arow + 16 * 80);
        ldmat4(al[0], sbase + xl + arow);
        ldmat4(al[1], sbase + xl + arow + 16 * 80);
#pragma unroll
        for (int nt = 0; nt < 4; nt++) {
            uint2 h2 = __ldg(&wH2[(ks * 4 + nt) * 32 + lane]);
            uint2 l2 = __ldg(&wL2[(ks * 4 + nt) * 32 + lane]);
#pragma unroll
            for (int mt = 0; mt < 2; mt++) {
                mma16816(acc[mt][nt], ah[mt], h2.x, h2.y);
                mma16816(acc[mt][nt], ah[mt], l2.x, l2.y);
                mma16816(acc[mt][nt], al[mt], h2.x, h2.y);
            }
        }
    }
}

__global__ void __launch_bounds__(512, 1) k_conv_t(const float* __restrict__ X,
                                                   const float* __restrict__ in_w,
                                                   const float* __restrict__ in_b,
                                                   const float* __restrict__ ct_b,
                                                   const float* __restrict__ cs_b) {
    extern __shared__ char smem[];
    uint32_t sbase = smem_u32(smem);
    int tid = threadIdx.x, lane = tid & 31, warp = tid >> 5;
    int bn = blockIdx.x, b = bn >> 7, n = bn & 127;
    int tau0w = warp * 32;
    // tcn destination constants for this block's node n
    int nG = n >> 4, nRG = (n >> 3) & 1, nL4 = (n & 7) << 2;

    // zero causal pads for XAH/XAL/XBH now (XBL region holds proj temp)
    if (tid < 160) {
        ((uint32_t*)(smem + XAH_B))[tid] = 0;
        ((uint32_t*)(smem + XAL_B))[tid] = 0;
        ((uint32_t*)(smem + XBH_B))[tid] = 0;
    }
    // ---- stage proj temp: raw X rows (contiguous!) + weights + bias ----
    {
        float* sXin = (float*)(smem + TXI_B);
        const float* Xb = X + (size_t)bn * 8192;  // 512 rows x 16 floats
        for (int i = tid; i < 8192; i += 512) {
            int t = i >> 4, f = i & 15;
            sXin[t * 17 + f] = Xb[i];
        }
        float* sWin = (float*)(smem + TWI_B);
        for (int i = tid; i < 1024; i += 512) {
            int f = i >> 6, o = i & 63;
            sWin[i] = in_w[f * 96 + o];
        }
        if (tid < 64) ((float*)(smem + TBI_B))[tid] = in_b[tid];
    }
    __syncthreads();

    // ---- in-kernel proj: thread = (col-pair tcp, tau-group) ----
    uint32_t xbl_st[16];
    {
        const float* sXin = (const float*)(smem + TXI_B);
        const float* sWin = (const float*)(smem + TWI_B);
        const float* sBin = (const float*)(smem + TBI_B);
        int tcp = tid & 15, tt0 = tid >> 4;
        float wa0[16], wa1[16], wb0[16], wb1[16];
#pragma unroll
        for (int f = 0; f < 16; f++) {
            const float* wr = sWin + f * 64 + 2 * tcp;
            wa0[f] = wr[0]; wa1[f] = wr[1];
            wb0[f] = wr[32]; wb1[f] = wr[33];
        }
        float ba0 = sBin[2 * tcp], ba1 = sBin[2 * tcp + 1];
        float bb0 = sBin[32 + 2 * tcp], bb1 = sBin[32 + 2 * tcp + 1];
#pragma unroll 2
        for (int it = 0; it < 16; it++) {
            int tau = it * 32 + tt0;
            const float* xr = sXin + tau * 17;
            float a0 = ba0, a1 = ba1, b0v = bb0, b1v = bb1;
#pragma unroll
            for (int f = 0; f < 16; f++) {
                float xv = xr[f];
                a0 = fmaf(xv, wa0[f], a0);
                a1 = fmaf(xv, wa1[f], a1);
                b0v = fmaf(xv, wb0[f], b0v);
                b1v = fmaf(xv, wb1[f], b1v);
            }
            uint32_t hw, lw;
            uint32_t w = (uint32_t)((8 + tau) * 20 + tcp);
            split2(a0, a1, hw, lw);
            ((uint32_t*)(smem + XAH_B))[w] = hw;
            ((uint32_t*)(smem + XAL_B))[w] = lw;
            split2(b0v, b1v, hw, xbl_st[it]);
            ((uint32_t*)(smem + XBH_B))[w] = hw;
        }
    }
    __syncthreads();  // proj temp reads done -> XBL region reusable
    if (tid < 160) ((uint32_t*)(smem + XBL_B))[tid] = 0;
    {
        int tcp = tid & 15, tt0 = tid >> 4;
#pragma unroll
        for (int it = 0; it < 16; it++) {
            uint32_t w = (uint32_t)((8 + it * 32 + tt0) * 20 + tcp);
            ((uint32_t*)(smem + XBL_B))[w] = xbl_st[it];
        }
    }
    __syncthreads();  // XBL staged; layers are barrier-free from here

#pragma unroll 1
    for (int l = 0; l < 4; l++) {
        int d = 1 << l;
        float ta[2][4][4];
        conv_mma(sbase, XAH_B, XAL_B, (const uint2*)(g_cwH + (l * 2) * 1024),
                 (const uint2*)(g_cwL + (l * 2) * 1024), ct_b + l * 32, tau0w,
                 lane, d, ta);
        // stash t = exp(-2|a|) with sign of a (division deferred past conv B)
#pragma unroll
        for (int mt = 0; mt < 2; mt++)
#pragma unroll
            for (int nt = 0; nt < 4; nt++)
#pragma unroll
                for (int q = 0; q < 4; q++) {
                    float a = ta[mt][nt][q];
                    ta[mt][nt][q] = copysignf(__expf(-2.f * fabsf(a)), a);
                }
        float sg[2][4][4];
        conv_mma(sbase, XBH_B, XBL_B, (const uint2*)(g_cwH + (l * 2 + 1) * 1024),
                 (const uint2*)(g_cwL + (l * 2 + 1) * 1024), cs_b + l * 32, tau0w,
                 lane, d, sg);

        float2* tl2 = (float2*)g_tcn + (size_t)l * TCN_L2;
#pragma unroll
        for (int mt = 0; mt < 2; mt++)
#pragma unroll
            for (int nt = 0; nt < 4; nt++) {
                float v[4];
#pragma unroll
                for (int q = 0; q < 4; q++) {
                    float ts = ta[mt][nt][q];
                    float t = fabsf(ts);
                    float u = __expf(-sg[mt][nt][q]);
                    float r = copysignf(1.f - t, ts) *
                              __fdividef(1.f, (1.f + t) * (1.f + u));
                    v[q] = r;
                }
                int r0 = tau0w + mt * 16 + (lane >> 2);
                size_t da = (((size_t)(b * 512 + r0) * 8 + nG) * 8 + nt * 2 + nRG)
                                * 32 + nL4 + (lane & 3);
                tl2[da] = make_float2(v[0], v[1]);
                tl2[da + 16384] = make_float2(v[2], v[3]);  // r0+8: +8*8*8*32
            }
    }
}

// ---------------------------------------------------------------------------
// K3: fused x_res proj + fully-HMMA layer chain.
// tcn read in frag order (8 coalesced LDG.64 per layer per lane).
// ---------------------------------------------------------------------------
#define SXH_B   0         // X^T hi bf16 [32 o][136 j]
#define SXL_B   8704
#define K3_SMEM 17408

__device__ __forceinline__ void gemm32(float d[4][4], const uint32_t ah[2][4],
                                       const uint32_t al[2][4],
                                       const uint2* __restrict__ wH,
                                       const uint2* __restrict__ wL,
                                       int lane) {
#pragma unroll
    for (int kc = 0; kc < 2; kc++)
#pragma unroll
        for (int nt = 0; nt < 4; nt++) {
            uint2 h2 = __ldg(&wH[(kc * 4 + nt) * 32 + lane]);
            uint2 l2 = __ldg(&wL[(kc * 4 + nt) * 32 + lane]);
            mma16816(d[nt], ah[kc], h2.x, h2.y);
            mma16816(d[nt], ah[kc], l2.x, l2.y);
            mma16816(d[nt], al[kc], h2.x, h2.y);
        }
}
__device__ __forceinline__ void conv_frags(const float d[4][4], uint32_t ah[2][4],
                                           uint32_t al[2][4]) {
#pragma unroll
    for (int kc = 0; kc < 2; kc++)
#pragma unroll
        for (int r = 0; r < 4; r++) {
            int nt = 2 * kc + (r >> 1), qs = (r & 1) * 2;
            split2(d[nt][qs], d[nt][qs + 1], ah[kc][r], al[kc][r]);
        }
}
__device__ __forceinline__ void bias_add(float d[4][4],
                                         const float* __restrict__ bptr,
                                         int lane) {
#pragma unroll
    for (int nt = 0; nt < 4; nt++) {
        float2 bv = __ldg((const float2*)(bptr + nt * 8 + 2 * (lane & 3)));
        d[nt][0] += bv.x; d[nt][1] += bv.y;
        d[nt][2] += bv.x; d[nt][3] += bv.y;
    }
}

__global__ void __launch_bounds__(256, 2) k_layers_f(
    const float* __restrict__ X, const float* __restrict__ in_w,
    const float* __restrict__ in_b, const float* __restrict__ gcn_b,
    const float* __restrict__ res_b, const float* __restrict__ skip_b,
    const float* __restrict__ out1_b, const float* __restrict__ out2_b,
    float* __restrict__ out) {
    extern __shared__ char smem[];
    uint32_t sbase = smem_u32(smem);
    int tid = threadIdx.x;
    int lane = tid & 31;
    int g = tid >> 5;
    int row0 = g * 16;
    int bt = blockIdx.x;

    // ---- x_res proj: temp in SXH/SXL region (dead until first X-split) ----
    float xres[4][4];
    {
        float* sXin = (float*)(smem);            // 128*17 floats = 8704 B
        float* sWin = (float*)(smem + 8704);     // 16*32 floats  = 2048 B
        float* sBin = (float*)(smem + 10752);    // 32 floats
        const float* Xbt = X + (size_t)bt * 2048;  // contiguous [128][16]
        for (int i = tid; i < 2048; i += 256) {
            int nn = i >> 4, f = i & 15;
            sXin[nn * 17 + f] = Xbt[i];
        }
        for (int i = tid; i < 512; i += 256) {
            int f = i >> 5, o = i & 31;
            sWin[i] = in_w[f * 96 + 64 + o];
        }
        if (tid < 32) sBin[tid] = in_b[64 + tid];
        __syncthreads();
#pragma unroll
        for (int nt = 0; nt < 4; nt++) {
            int oc0 = nt * 8 + 2 * (lane & 3);
            float b0 = sBin[oc0], b1 = sBin[oc0 + 1];
#pragma unroll
            for (int rg = 0; rg < 2; rg++) {
                int ic = row0 + (lane >> 2) + rg * 8;
                const float* xr = sXin + ic * 17;
                float s0 = b0, s1 = b1;
#pragma unroll
                for (int f = 0; f < 16; f++) {
                    float xv = xr[f];
                    s0 = fmaf(xv, sWin[f * 32 + oc0], s0);
                    s1 = fmaf(xv, sWin[f * 32 + oc0 + 1], s1);
                }
                xres[nt][rg * 2] = s0;
                xres[nt][rg * 2 + 1] = s1;
            }
        }
        __syncthreads();  // temp reads done before X-split overwrites
    }

    // ---- B-operand ldmatrix addressing (X-split smem) ----
    int bn_row = ((lane >> 4) << 3) + (lane & 7);
    int bk_half = (lane >> 3) & 1;
    uint32_t bh_base =
        sbase + SXH_B + (uint32_t)((bn_row * 136 + bk_half * 8) * 2);
    uint32_t bl_base =
        sbase + SXL_B + (uint32_t)((bn_row * 136 + bk_half * 8) * 2);

    float skip[4][4];
#pragma unroll
    for (int nt = 0; nt < 4; nt++)
#pragma unroll
        for (int q = 0; q < 4; q++) skip[nt][q] = 0.f;

    const uint4* aH4 = (const uint4*)g_afragH;
    const uint4* aL4 = (const uint4*)g_afragL;

    for (int l = 0; l < 4; l++) {
        // ---- X-split write from xres frags into SXH/SXL ----
#pragma unroll
        for (int nt = 0; nt < 4; nt++)
#pragma unroll
            for (int q = 0; q < 4; q++) {
                int oc = nt * 8 + 2 * (lane & 3) + (q & 1);
                int ic = row0 + (lane >> 2) + (q >> 1) * 8;
                float v = xres[nt][q];
                __nv_bfloat16 hi = __float2bfloat16(v);
                __nv_bfloat16 lo = __float2bfloat16(v - __bfloat162float(hi));
                *(__nv_bfloat16*)(smem + SXH_B + (oc * 136 + ic) * 2) = hi;
                *(__nv_bfloat16*)(smem + SXL_B + (oc * 136 + ic) * 2) = lo;
            }
        __syncthreads();  // (1) X-split visible

        // ---- A-mix MMA: acc = A @ X (3-pass split); A frags via LDG ----
        float acc[4][4];
#pragma unroll
        for (int nt = 0; nt < 4; nt++)
#pragma unroll
            for (int q = 0; q < 4; q++) acc[nt][q] = 0.f;
#pragma unroll
        for (int ks = 0; ks < 8; ks++) {
            uint32_t kb = (uint32_t)(ks * 32);
            uint32_t ah[4], al[4], bh[2][4], bl[2][4];
            uint4 va = __ldg(&aH4[(g * 8 + ks) * 32 + lane]);
            uint4 vl = __ldg(&aL4[(g * 8 + ks) * 32 + lane]);
            ah[0] = va.x; ah[1] = va.y; ah[2] = va.z; ah[3] = va.w;
            al[0] = vl.x; al[1] = vl.y; al[2] = vl.z; al[3] = vl.w;
            ldmat4(bh[0], bh_base + kb);
            ldmat4(bh[1], bh_base + 16 * 272 + kb);
            ldmat4(bl[0], bl_base + kb);
            ldmat4(bl[1], bl_base + 16 * 272 + kb);
#pragma unroll
            for (int nt = 0; nt < 4; nt++) {
                uint32_t b0h = bh[nt >> 1][(nt & 1) * 2];
                uint32_t b1h = bh[nt >> 1][(nt & 1) * 2 + 1];
                uint32_t b0l = bl[nt >> 1][(nt & 1) * 2];
                uint32_t b1l = bl[nt >> 1][(nt & 1) * 2 + 1];
                mma16816(acc[nt], ah, b0h, b1h);
                mma16816(acc[nt], ah, b0l, b1l);
                mma16816(acc[nt], al, b0h, b1h);
            }
        }
        __syncthreads();  // (2) ldmatrix reads done (next layer rewrites X)

        // ---- gcn: h = AX @ gcn_w + gcn_b + tcn ----
        uint32_t fh[2][4], fl[2][4];
        conv_frags(acc, fh, fl);
        float h[4][4];
#pragma unroll
        for (int nt = 0; nt < 4; nt++) {
            float2 bv = __ldg((const float2*)(gcn_b + l * 32 + nt * 8 +
                                              2 * (lane & 3)));
            h[nt][0] = bv.x; h[nt][1] = bv.y;
            h[nt][2] = bv.x; h[nt][3] = bv.y;
        }
        gemm32(h, fh, fl, (const uint2*)(g_wH32 + (l * 3) * 512),
               (const uint2*)(g_wL32 + (l * 3) * 512), lane);
        {
            // tcn in frag order: coalesced float2 per (nt, rg)
            const float2* tp = (const float2*)g_tcn + (size_t)l * TCN_L2 +
                               ((size_t)bt * 8 + g) * 256;
#pragma unroll
            for (int nt = 0; nt < 4; nt++)
#pragma unroll
                for (int rg = 0; rg < 2; rg++) {
                    float2 tv = __ldg(&tp[(nt * 2 + rg) * 32 + lane]);
                    h[nt][rg * 2] += tv.x;
                    h[nt][rg * 2 + 1] += tv.y;
                }
        }
        // ---- skip += h @ skip_w + b ;  xres += h @ res_w + b ----
        conv_frags(h, fh, fl);
        bias_add(skip, skip_b + l * 32, lane);
        gemm32(skip, fh, fl, (const uint2*)(g_wH32 + (l * 3 + 1) * 512),
               (const uint2*)(g_wL32 + (l * 3 + 1) * 512), lane);
        bias_add(xres, res_b + l * 32, lane);
        gemm32(xres, fh, fl, (const uint2*)(g_wH32 + (l * 3 + 2) * 512),
               (const uint2*)(g_wL32 + (l * 3 + 2) * 512), lane);
    }

    // ---- head (all operands in regs/global; no barriers) ----
    {
        uint32_t fh[2][4], fl[2][4];
#pragma unroll
        for (int nt = 0; nt < 4; nt++)
#pragma unroll
            for (int q = 0; q < 4; q++) skip[nt][q] = fmaxf(skip[nt][q], 0.f);
        conv_frags(skip, fh, fl);
        float h2[4][4];
#pragma unroll
        for (int nt = 0; nt < 4; nt++) {
            float2 bv = __ldg((const float2*)(out1_b + nt * 8 + 2 * (lane & 3)));
            h2[nt][0] = bv.x; h2[nt][1] = bv.y;
            h2[nt][2] = bv.x; h2[nt][3] = bv.y;
        }
        gemm32(h2, fh, fl, (const uint2*)(g_wH32 + 6144),
               (const uint2*)(g_wL32 + 6144), lane);
#pragma unroll
        for (int nt = 0; nt < 4; nt++)
#pragma unroll
            for (int q = 0; q < 4; q++) h2[nt][q] = fmaxf(h2[nt][q], 0.f);
        conv_frags(h2, fh, fl);

        float o2[2][4];
#pragma unroll
        for (int nt = 0; nt < 2; nt++) {
            float2 bv = __ldg((const float2*)(out2_b + nt * 8 + 2 * (lane & 3)));
            o2[nt][0] = bv.x; o2[nt][1] = bv.y;
            o2[nt][2] = bv.x; o2[nt][3] = bv.y;
        }
        const uint2* w2H = (const uint2*)(g_wH32 + 6656);
        const uint2* w2L = (const uint2*)(g_wL32 + 6656);
#pragma unroll
        for (int kc = 0; kc < 2; kc++)
#pragma unroll
            for (int nt = 0; nt < 2; nt++) {
                uint2 h2w = __ldg(&w2H[(kc * 2 + nt) * 32 + lane]);
                uint2 l2w = __ldg(&w2L[(kc * 2 + nt) * 32 + lane]);
                mma16816(o2[nt], fh[kc], h2w.x, h2w.y);
                mma16816(o2[nt], fh[kc], l2w.x, l2w.y);
                mma16816(o2[nt], fl[kc], h2w.x, h2w.y);
            }
        float* op = out + (size_t)bt * 2048;
#pragma unroll
        for (int nt = 0; nt < 2; nt++)
#pragma unroll
            for (int rg = 0; rg < 2; rg++)
                *(float2*)(op + (size_t)(row0 + (lane >> 2) + rg * 8) * 16 +
                           nt * 8 + 2 * (lane & 3)) =
                    make_float2(o2[nt][rg * 2], o2[nt][rg * 2 + 1]);
    }
}

// ---------------------------------------------------------------------------
extern "C" void kernel_launch(void* const* d_in, const int* in_sizes, int n_in,
                              void* d_out, int out_size) {
    const float* X = (const float*)d_in[0];
    const float* A = (const float*)d_in[1];
    const float* in_w = (const float*)d_in[2];
    const float* in_b = (const float*)d_in[3];
    const float* ct_w = (const float*)d_in[4];
    const float* ct_b = (const float*)d_in[5];
    const float* cs_w = (const float*)d_in[6];
    const float* cs_b = (const float*)d_in[7];
    const float* gcn_w = (const float*)d_in[8];
    const float* gcn_b = (const float*)d_in[9];
    const float* res_w = (const float*)d_in[10];
    const float* res_b = (const float*)d_in[11];
    const float* skip_w = (const float*)d_in[12];
    const float* skip_b = (const float*)d_in[13];
    const float* out1_w = (const float*)d_in[14];
    const float* out1_b = (const float*)d_in[15];
    const float* out2_w = (const float*)d_in[16];
    const float* out2_b = (const float*)d_in[17];
    float* out = (float*)d_out;

    cudaFuncSetAttribute(k_conv_t, cudaFuncAttributeMaxDynamicSharedMemorySize,
                         K2_SMEM);
    cudaFuncSetAttribute(k_layers_f, cudaFuncAttributeMaxDynamicSharedMemorySize,
                         K3_SMEM);

    k_prep<<<128, 256>>>(A, gcn_w, skip_w, res_w, out1_w, out2_w, ct_w, cs_w);
    k_conv_t<<<1024, 512, K2_SMEM>>>(X, in_w, in_b, ct_b, cs_b);
    k_layers_f<<<4096, 256, K3_SMEM>>>(X, in_w, in_b, gcn_b, res_b, skip_b,
                                       out1_b, out2_b, out);
}

// round 17
// speedup vs baseline: 1.0077x; 1.0077x over previous
#include <cuda_runtime.h>
#include <cuda_bf16.h>
#include <math.h>
#include <stdint.h>

// Problem constants: B=8, T=512, N=128, F=16, H=32, L=4
#define BTNH_ 16777216ull   // 8*512*128*32

// Scratch (allocation-free: static device globals)
__device__ float g_tcn[4ull * 16777216ull];  // [l][b][t][n][o]
// Precomputed constant fragments (filled by k_prep each launch)
__device__ uint32_t g_afragH[8192];  // A frags: [mt8][ks8][lane32][4]
__device__ uint32_t g_afragL[8192];
__device__ uint32_t g_wH32[6912];    // gemm wts: 12x512 + out1@6144 + out2@6656
__device__ uint32_t g_wL32[6912];
__device__ uint32_t g_cwH[8192];     // conv wts: [(l*2+conv)]x1024
__device__ uint32_t g_cwL[8192];

// ====================== common helpers ======================
__device__ __forceinline__ uint32_t smem_u32(const void* p) {
    uint32_t a;
    asm("{ .reg .u64 t; cvta.to.shared.u64 t, %1; cvt.u32.u64 %0, t; }"
        : "=r"(a) : "l"(p));
    return a;
}
__device__ __forceinline__ void ldmat4(uint32_t r[4], uint32_t addr) {
    asm volatile("ldmatrix.sync.aligned.m8n8.x4.shared.b16 {%0,%1,%2,%3}, [%4];"
                 : "=r"(r[0]), "=r"(r[1]), "=r"(r[2]), "=r"(r[3]) : "r"(addr));
}
__device__ __forceinline__ void mma16816(float d[4], const uint32_t a[4],
                                         uint32_t b0, uint32_t b1) {
    asm volatile(
        "mma.sync.aligned.m16n8k16.row.col.f32.bf16.bf16.f32 "
        "{%0,%1,%2,%3}, {%4,%5,%6,%7}, {%8,%9}, {%0,%1,%2,%3};"
        : "+f"(d[0]), "+f"(d[1]), "+f"(d[2]), "+f"(d[3])
        : "r"(a[0]), "r"(a[1]), "r"(a[2]), "r"(a[3]), "r"(b0), "r"(b1));
}
__device__ __forceinline__ uint32_t pack_bf16(__nv_bfloat16 lo, __nv_bfloat16 hi) {
    return (uint32_t)__bfloat16_as_ushort(lo) |
           ((uint32_t)__bfloat16_as_ushort(hi) << 16);
}
__device__ __forceinline__ void split2(float v0, float v1, uint32_t& hw,
                                       uint32_t& lw) {
    __nv_bfloat16 h0 = __float2bfloat16(v0), h1 = __float2bfloat16(v1);
    hw = pack_bf16(h0, h1);
    lw = pack_bf16(__float2bfloat16(v0 - __bfloat162float(h0)),
                   __float2bfloat16(v1 - __bfloat162float(h1)));
}

// ---------------------------------------------------------------------------
// K0: fragment prep — A frags, gemm-weight frags, conv-weight frags.
// ---------------------------------------------------------------------------
__global__ void k_prep(const float* __restrict__ A,
                       const float* __restrict__ gcn_w,
                       const float* __restrict__ skip_w,
                       const float* __restrict__ res_w,
                       const float* __restrict__ out1_w,
                       const float* __restrict__ out2_w,
                       const float* __restrict__ ct_w,
                       const float* __restrict__ cs_w) {
    int tid = blockIdx.x * blockDim.x + threadIdx.x;
    int nthr = gridDim.x * blockDim.x;

    // A frags: m16n8k16 A-operand layout, 8 mtiles x 8 ks x 32 lanes x 4 words
    for (int idx = tid; idx < 2048; idx += nthr) {
        int mt = idx >> 8, ks = (idx >> 5) & 7, lane = idx & 31;
        int r = lane >> 2, c = lane & 3;
        int row = mt * 16 + r, k = ks * 16 + 2 * c;
        uint32_t base = (uint32_t)idx * 4;
#pragma unroll
        for (int j = 0; j < 4; j++) {
            int rr = row + (j & 1) * 8;
            int kk = k + (j >> 1) * 8;
            uint32_t hw, lw;
            split2(A[rr * 128 + kk], A[rr * 128 + kk + 1], hw, lw);
            g_afragH[base + j] = hw;
            g_afragL[base + j] = lw;
        }
    }
    // gemm weights: 13 matrices x 512 words (lane-keyed frag layout)
    for (int idx = tid; idx < 6656; idx += nthr) {
        int m = idx >> 9, i = idx & 511;
        const float* W;
        if (m == 12) W = out1_w;
        else {
            int l = m / 3, kind = m % 3;
            W = (kind == 0 ? gcn_w : kind == 1 ? skip_w : res_w) + l * 1024;
        }
        int cp = i >> 5, o = i & 31;
        uint32_t hw, lw;
        split2(W[(2 * cp) * 32 + o], W[(2 * cp + 1) * 32 + o], hw, lw);
        int kc = cp >> 3, r = cp & 7;
        int e = (kc * 4 + (o >> 3)) * 32 + (((o & 7) << 2) | (r & 3));
        int slot = m * 512 + e * 2 + (r >> 2);
        g_wH32[slot] = hw;
        g_wL32[slot] = lw;
    }
    // out2: 256 words at offset 6656
    for (int idx = tid; idx < 256; idx += nthr) {
        int cp = idx >> 4, o = idx & 15;
        uint32_t hw, lw;
        split2(out2_w[(2 * cp) * 16 + o], out2_w[(2 * cp + 1) * 16 + o], hw, lw);
        int kc = cp >> 3, r = cp & 7;
        int e = (kc * 2 + (o >> 3)) * 32 + (((o & 7) << 2) | (r & 3));
        g_wH32[6656 + e * 2 + (r >> 2)] = hw;
        g_wL32[6656 + e * 2 + (r >> 2)] = lw;
    }
    // conv weights: 8 matrices (l*2+conv) x 1024 words
    for (int idx = tid; idx < 8192; idx += nthr) {
        int cv = idx >> 10, i = idx & 1023;
        int l = cv >> 1;
        const float* W = ((cv & 1) ? cs_w : ct_w) + l * 2048;
        int krow = i >> 5, o = i & 31;
        int k0 = krow * 2;
        const float* src = W + (k0 >> 5) * 1024 + (k0 & 31) * 32 + o;
        uint32_t hw, lw;
        split2(src[0], src[32], hw, lw);
        int ks = krow >> 3, r = krow & 7;
        int e = (ks * 4 + (o >> 3)) * 32 + (((o & 7) << 2) | (r & 3));
        int slot = cv * 1024 + e * 2 + (r >> 2);
        g_cwH[slot] = hw;
        g_cwL[slot] = lw;
    }
}

// ---------------------------------------------------------------------------
// K2: fused input-proj (x_a/x_b) + gated dilated causal convs (HMMA).
// Gate = copysign(1-t, a) * rcp((1+t)(1+u)): one MUFU.RCP per value.
// tcn layout: round-15 [l][b][t][n][o] (round-16 frag-order relayout reverted).
// ---------------------------------------------------------------------------
#define XAH_B 0
#define XAL_B 41600
#define XBH_B 83200
#define XBL_B 124800
#define K2_SMEM 166400
// proj temp (inside XBL region, 41600 B available)
#define TXI_B XBL_B            // 512*17 floats = 34816 B
#define TWI_B (XBL_B + 34816)  // 16*64 floats  = 4096 B
#define TBI_B (XBL_B + 38912)  // 64 floats     = 256 B

__device__ __forceinline__ void conv_mma(uint32_t sbase,
                                         uint32_t xh, uint32_t xl,
                                         const uint2* __restrict__ wH2,
                                         const uint2* __restrict__ wL2,
                                         const float* __restrict__ bias,
                                         int tau0w, int lane, int d,
                                         float acc[2][4][4]) {
#pragma unroll
    for (int nt = 0; nt < 4; nt++) {
        float2 bv = __ldg((const float2*)(bias + nt * 8 + (lane & 3) * 2));
#pragma unroll
        for (int mt = 0; mt < 2; mt++) {
            acc[mt][nt][0] = bv.x; acc[mt][nt][1] = bv.y;
            acc[mt][nt][2] = bv.x; acc[mt][nt][3] = bv.y;
        }
    }
    int rbase = 8 + tau0w + (lane & 15);
    int chan = (lane >> 4) * 8;
#pragma unroll
    for (int ks = 0; ks < 4; ks++) {
        int tsh = (ks < 2) ? d : 0;
        int ch = chan + (ks & 1) * 16;
        uint32_t arow = (uint32_t)((rbase - tsh) * 80 + ch * 2);
        uint32_t ah[2][4], al[2][4];
        ldmat4(ah[0], sbase + xh + arow);
        ldmat4(ah[1], sbase + xh + arow + 16 * 80);
        ldmat4(al[0], sbase + xl + arow);
        ldmat4(al[1], sbase + xl + arow + 16 * 80);
#pragma unroll
        for (int nt = 0; nt < 4; nt++) {
            uint2 h2 = __ldg(&wH2[(ks * 4 + nt) * 32 + lane]);
            uint2 l2 = __ldg(&wL2[(ks * 4 + nt) * 32 + lane]);
#pragma unroll
            for (int mt = 0; mt < 2; mt++) {
                mma16816(acc[mt][nt], ah[mt], h2.x, h2.y);
                mma16816(acc[mt][nt], ah[mt], l2.x, l2.y);
                mma16816(acc[mt][nt], al[mt], h2.x, h2.y);
            }
        }
    }
}

__global__ void __launch_bounds__(512, 1) k_conv_t(const float* __restrict__ X,
                                                   const float* __restrict__ in_w,
                                                   const float* __restrict__ in_b,
                                                   const float* __restrict__ ct_b,
                                                   const float* __restrict__ cs_b) {
    extern __shared__ char smem[];
    uint32_t sbase = smem_u32(smem);
    int tid = threadIdx.x, lane = tid & 31, warp = tid >> 5;
    int bn = blockIdx.x, b = bn >> 7, n = bn & 127;
    int tau0w = warp * 32;

    // zero causal pads for XAH/XAL/XBH now (XBL region holds proj temp)
    if (tid < 160) {
        ((uint32_t*)(smem + XAH_B))[tid] = 0;
        ((uint32_t*)(smem + XAL_B))[tid] = 0;
        ((uint32_t*)(smem + XBH_B))[tid] = 0;
    }
    // ---- stage proj temp: raw X rows (contiguous!) + weights + bias ----
    {
        float* sXin = (float*)(smem + TXI_B);
        const float* Xb = X + (size_t)bn * 8192;  // 512 rows x 16 floats
        for (int i = tid; i < 8192; i += 512) {
            int t = i >> 4, f = i & 15;
            sXin[t * 17 + f] = Xb[i];
        }
        float* sWin = (float*)(smem + TWI_B);
        for (int i = tid; i < 1024; i += 512) {
            int f = i >> 6, o = i & 63;
            sWin[i] = in_w[f * 96 + o];
        }
        if (tid < 64) ((float*)(smem + TBI_B))[tid] = in_b[tid];
    }
    __syncthreads();

    // ---- in-kernel proj: thread = (col-pair tcp, tau-group) ----
    uint32_t xbl_st[16];
    {
        const float* sXin = (const float*)(smem + TXI_B);
        const float* sWin = (const float*)(smem + TWI_B);
        const float* sBin = (const float*)(smem + TBI_B);
        int tcp = tid & 15, tt0 = tid >> 4;
        float wa0[16], wa1[16], wb0[16], wb1[16];
#pragma unroll
        for (int f = 0; f < 16; f++) {
            const float* wr = sWin + f * 64 + 2 * tcp;
            wa0[f] = wr[0]; wa1[f] = wr[1];
            wb0[f] = wr[32]; wb1[f] = wr[33];
        }
        float ba0 = sBin[2 * tcp], ba1 = sBin[2 * tcp + 1];
        float bb0 = sBin[32 + 2 * tcp], bb1 = sBin[32 + 2 * tcp + 1];
#pragma unroll 2
        for (int it = 0; it < 16; it++) {
            int tau = it * 32 + tt0;
            const float* xr = sXin + tau * 17;
            float a0 = ba0, a1 = ba1, b0v = bb0, b1v = bb1;
#pragma unroll
            for (int f = 0; f < 16; f++) {
                float xv = xr[f];
                a0 = fmaf(xv, wa0[f], a0);
                a1 = fmaf(xv, wa1[f], a1);
                b0v = fmaf(xv, wb0[f], b0v);
                b1v = fmaf(xv, wb1[f], b1v);
            }
            uint32_t hw, lw;
            uint32_t w = (uint32_t)((8 + tau) * 20 + tcp);
            split2(a0, a1, hw, lw);
            ((uint32_t*)(smem + XAH_B))[w] = hw;
            ((uint32_t*)(smem + XAL_B))[w] = lw;
            split2(b0v, b1v, hw, xbl_st[it]);
            ((uint32_t*)(smem + XBH_B))[w] = hw;
        }
    }
    __syncthreads();  // proj temp reads done -> XBL region reusable
    if (tid < 160) ((uint32_t*)(smem + XBL_B))[tid] = 0;
    {
        int tcp = tid & 15, tt0 = tid >> 4;
#pragma unroll
        for (int it = 0; it < 16; it++) {
            uint32_t w = (uint32_t)((8 + it * 32 + tt0) * 20 + tcp);
            ((uint32_t*)(smem + XBL_B))[w] = xbl_st[it];
        }
    }
    __syncthreads();  // XBL staged; layers are barrier-free from here

#pragma unroll 1
    for (int l = 0; l < 4; l++) {
        int d = 1 << l;
        float ta[2][4][4];
        conv_mma(sbase, XAH_B, XAL_B, (const uint2*)(g_cwH + (l * 2) * 1024),
                 (const uint2*)(g_cwL + (l * 2) * 1024), ct_b + l * 32, tau0w,
                 lane, d, ta);
        // stash t = exp(-2|a|) with sign of a (reciprocal deferred past conv B)
#pragma unroll
        for (int mt = 0; mt < 2; mt++)
#pragma unroll
            for (int nt = 0; nt < 4; nt++)
#pragma unroll
                for (int q = 0; q < 4; q++) {
                    float a = ta[mt][nt][q];
                    ta[mt][nt][q] = copysignf(__expf(-2.f * fabsf(a)), a);
                }
        float sg[2][4][4];
        conv_mma(sbase, XBH_B, XBL_B, (const uint2*)(g_cwH + (l * 2 + 1) * 1024),
                 (const uint2*)(g_cwL + (l * 2 + 1) * 1024), cs_b + l * 32, tau0w,
                 lane, d, sg);

        float* outl = g_tcn + (size_t)l * BTNH_ + ((size_t)b * 512) * 4096 + n * 32;
#pragma unroll
        for (int mt = 0; mt < 2; mt++)
#pragma unroll
            for (int nt = 0; nt < 4; nt++) {
                float v[4];
#pragma unroll
                for (int q = 0; q < 4; q++) {
                    float ts = ta[mt][nt][q];
                    float t = fabsf(ts);
                    float u = __expf(-sg[mt][nt][q]);
                    v[q] = copysignf(1.f - t, ts) *
                           __fdividef(1.f, (1.f + t) * (1.f + u));
                }
                int r = tau0w + mt * 16 + (lane >> 2);
                int o0 = nt * 8 + (lane & 3) * 2;
                *(float2*)(outl + (size_t)r * 4096 + o0) = make_float2(v[0], v[1]);
                *(float2*)(outl + (size_t)(r + 8) * 4096 + o0) =
                    make_float2(v[2], v[3]);
            }
    }
}

// ---------------------------------------------------------------------------
// K3: fused x_res proj + fully-HMMA layer chain (round-15 form, unchanged).
// ---------------------------------------------------------------------------
#define SXH_B   0         // X^T hi bf16 [32 o][136 j]
#define SXL_B   8704
#define K3_SMEM 17408

__device__ __forceinline__ void gemm32(float d[4][4], const uint32_t ah[2][4],
                                       const uint32_t al[2][4],
                                       const uint2* __restrict__ wH,
                                       const uint2* __restrict__ wL,
                                       int lane) {
#pragma unroll
    for (int kc = 0; kc < 2; kc++)
#pragma unroll
        for (int nt = 0; nt < 4; nt++) {
            uint2 h2 = __ldg(&wH[(kc * 4 + nt) * 32 + lane]);
            uint2 l2 = __ldg(&wL[(kc * 4 + nt) * 32 + lane]);
            mma16816(d[nt], ah[kc], h2.x, h2.y);
            mma16816(d[nt], ah[kc], l2.x, l2.y);
            mma16816(d[nt], al[kc], h2.x, h2.y);
        }
}
__device__ __forceinline__ void conv_frags(const float d[4][4], uint32_t ah[2][4],
                                           uint32_t al[2][4]) {
#pragma unroll
    for (int kc = 0; kc < 2; kc++)
#pragma unroll
        for (int r = 0; r < 4; r++) {
            int nt = 2 * kc + (r >> 1), qs = (r & 1) * 2;
            split2(d[nt][qs], d[nt][qs + 1], ah[kc][r], al[kc][r]);
        }
}
__device__ __forceinline__ void bias_add(float d[4][4],
                                         const float* __restrict__ bptr,
                                         int lane) {
#pragma unroll
    for (int nt = 0; nt < 4; nt++) {
        float2 bv = __ldg((const float2*)(bptr + nt * 8 + 2 * (lane & 3)));
        d[nt][0] += bv.x; d[nt][1] += bv.y;
        d[nt][2] += bv.x; d[nt][3] += bv.y;
    }
}

__global__ void __launch_bounds__(256, 2) k_layers_f(
    const float* __restrict__ X, const float* __restrict__ in_w,
    const float* __restrict__ in_b, const float* __restrict__ gcn_b,
    const float* __restrict__ res_b, const float* __restrict__ skip_b,
    const float* __restrict__ out1_b, const float* __restrict__ out2_b,
    float* __restrict__ out) {
    extern __shared__ char smem[];
    uint32_t sbase = smem_u32(smem);
    int tid = threadIdx.x;
    int lane = tid & 31;
    int g = tid >> 5;
    int row0 = g * 16;
    int bt = blockIdx.x;
    size_t base = (size_t)bt * 4096;

    // ---- x_res proj: temp in SXH/SXL region (dead until first X-split) ----
    float xres[4][4];
    {
        float* sXin = (float*)(smem);            // 128*17 floats = 8704 B
        float* sWin = (float*)(smem + 8704);     // 16*32 floats  = 2048 B
        float* sBin = (float*)(smem + 10752);    // 32 floats
        const float* Xbt = X + (size_t)bt * 2048;  // contiguous [128][16]
        for (int i = tid; i < 2048; i += 256) {
            int nn = i >> 4, f = i & 15;
            sXin[nn * 17 + f] = Xbt[i];
        }
        for (int i = tid; i < 512; i += 256) {
            int f = i >> 5, o = i & 31;
            sWin[i] = in_w[f * 96 + 64 + o];
        }
        if (tid < 32) sBin[tid] = in_b[64 + tid];
        __syncthreads();
#pragma unroll
        for (int nt = 0; nt < 4; nt++) {
            int oc0 = nt * 8 + 2 * (lane & 3);
            float b0 = sBin[oc0], b1 = sBin[oc0 + 1];
#pragma unroll
            for (int rg = 0; rg < 2; rg++) {
                int ic = row0 + (lane >> 2) + rg * 8;
                const float* xr = sXin + ic * 17;
                float s0 = b0, s1 = b1;
#pragma unroll
                for (int f = 0; f < 16; f++) {
                    float xv = xr[f];
                    s0 = fmaf(xv, sWin[f * 32 + oc0], s0);
                    s1 = fmaf(xv, sWin[f * 32 + oc0 + 1], s1);
                }
                xres[nt][rg * 2] = s0;
                xres[nt][rg * 2 + 1] = s1;
            }
        }
        __syncthreads();  // temp reads done before X-split overwrites
    }

    // ---- B-operand ldmatrix addressing (X-split smem) ----
    int bn_row = ((lane >> 4) << 3) + (lane & 7);
    int bk_half = (lane >> 3) & 1;
    uint32_t bh_base =
        sbase + SXH_B + (uint32_t)((bn_row * 136 + bk_half * 8) * 2);
    uint32_t bl_base =
        sbase + SXL_B + (uint32_t)((bn_row * 136 + bk_half * 8) * 2);

    float skip[4][4];
#pragma unroll
    for (int nt = 0; nt < 4; nt++)
#pragma unroll
        for (int q = 0; q < 4; q++) skip[nt][q] = 0.f;

    const uint4* aH4 = (const uint4*)g_afragH;
    const uint4* aL4 = (const uint4*)g_afragL;

    for (int l = 0; l < 4; l++) {
        // ---- X-split write from xres frags into SXH/SXL ----
#pragma unroll
        for (int nt = 0; nt < 4; nt++)
#pragma unroll
            for (int q = 0; q < 4; q++) {
                int oc = nt * 8 + 2 * (lane & 3) + (q & 1);
                int ic = row0 + (lane >> 2) + (q >> 1) * 8;
                float v = xres[nt][q];
                __nv_bfloat16 hi = __float2bfloat16(v);
                __nv_bfloat16 lo = __float2bfloat16(v - __bfloat162float(hi));
                *(__nv_bfloat16*)(smem + SXH_B + (oc * 136 + ic) * 2) = hi;
                *(__nv_bfloat16*)(smem + SXL_B + (oc * 136 + ic) * 2) = lo;
            }
        __syncthreads();  // (1) X-split visible

        // ---- A-mix MMA: acc = A @ X (3-pass split); A frags via LDG ----
        float acc[4][4];
#pragma unroll
        for (int nt = 0; nt < 4; nt++)
#pragma unroll
            for (int q = 0; q < 4; q++) acc[nt][q] = 0.f;
#pragma unroll
        for (int ks = 0; ks < 8; ks++) {
            uint32_t kb = (uint32_t)(ks * 32);
            uint32_t ah[4], al[4], bh[2][4], bl[2][4];
            uint4 va = __ldg(&aH4[(g * 8 + ks) * 32 + lane]);
            uint4 vl = __ldg(&aL4[(g * 8 + ks) * 32 + lane]);
            ah[0] = va.x; ah[1] = va.y; ah[2] = va.z; ah[3] = va.w;
            al[0] = vl.x; al[1] = vl.y; al[2] = vl.z; al[3] = vl.w;
            ldmat4(bh[0], bh_base + kb);
            ldmat4(bh[1], bh_base + 16 * 272 + kb);
            ldmat4(bl[0], bl_base + kb);
            ldmat4(bl[1], bl_base + 16 * 272 + kb);
#pragma unroll
            for (int nt = 0; nt < 4; nt++) {
                uint32_t b0h = bh[nt >> 1][(nt & 1) * 2];
                uint32_t b1h = bh[nt >> 1][(nt & 1) * 2 + 1];
                uint32_t b0l = bl[nt >> 1][(nt & 1) * 2];
                uint32_t b1l = bl[nt >> 1][(nt & 1) * 2 + 1];
                mma16816(acc[nt], ah, b0h, b1h);
                mma16816(acc[nt], ah, b0l, b1l);
                mma16816(acc[nt], al, b0h, b1h);
            }
        }
        __syncthreads();  // (2) ldmatrix reads done (next layer rewrites X)

        // ---- gcn: h = AX @ gcn_w + gcn_b + tcn ----
        uint32_t fh[2][4], fl[2][4];
        conv_frags(acc, fh, fl);
        float h[4][4];
#pragma unroll
        for (int nt = 0; nt < 4; nt++) {
            float2 bv = __ldg((const float2*)(gcn_b + l * 32 + nt * 8 +
                                              2 * (lane & 3)));
            h[nt][0] = bv.x; h[nt][1] = bv.y;
            h[nt][2] = bv.x; h[nt][3] = bv.y;
        }
        gemm32(h, fh, fl, (const uint2*)(g_wH32 + (l * 3) * 512),
               (const uint2*)(g_wL32 + (l * 3) * 512), lane);
        {
            const float* tcnp = g_tcn + (size_t)l * BTNH_ + base;
#pragma unroll
            for (int nt = 0; nt < 4; nt++)
#pragma unroll
                for (int rg = 0; rg < 2; rg++) {
                    float2 tv = *(const float2*)(tcnp +
                        (size_t)(row0 + (lane >> 2) + rg * 8) * 32 + nt * 8 +
                        2 * (lane & 3));
                    h[nt][rg * 2] += tv.x;
                    h[nt][rg * 2 + 1] += tv.y;
                }
        }
        // ---- skip += h @ skip_w + b ;  xres += h @ res_w + b ----
        conv_frags(h, fh, fl);
        bias_add(skip, skip_b + l * 32, lane);
        gemm32(skip, fh, fl, (const uint2*)(g_wH32 + (l * 3 + 1) * 512),
               (const uint2*)(g_wL32 + (l * 3 + 1) * 512), lane);
        bias_add(xres, res_b + l * 32, lane);
        gemm32(xres, fh, fl, (const uint2*)(g_wH32 + (l * 3 + 2) * 512),
               (const uint2*)(g_wL32 + (l * 3 + 2) * 512), lane);
    }

    // ---- head (all operands in regs/global; no barriers) ----
    {
        uint32_t fh[2][4], fl[2][4];
#pragma unroll
        for (int nt = 0; nt < 4; nt++)
#pragma unroll
            for (int q = 0; q < 4; q++) skip[nt][q] = fmaxf(skip[nt][q], 0.f);
        conv_frags(skip, fh, fl);
        float h2[4][4];
#pragma unroll
        for (int nt = 0; nt < 4; nt++) {
            float2 bv = __ldg((const float2*)(out1_b + nt * 8 + 2 * (lane & 3)));
            h2[nt][0] = bv.x; h2[nt][1] = bv.y;
            h2[nt][2] = bv.x; h2[nt][3] = bv.y;
        }
        gemm32(h2, fh, fl, (const uint2*)(g_wH32 + 6144),
               (const uint2*)(g_wL32 + 6144), lane);
#pragma unroll
        for (int nt = 0; nt < 4; nt++)
#pragma unroll
            for (int q = 0; q < 4; q++) h2[nt][q] = fmaxf(h2[nt][q], 0.f);
        conv_frags(h2, fh, fl);

        float o2[2][4];
#pragma unroll
        for (int nt = 0; nt < 2; nt++) {
            float2 bv = __ldg((const float2*)(out2_b + nt * 8 + 2 * (lane & 3)));
            o2[nt][0] = bv.x; o2[nt][1] = bv.y;
            o2[nt][2] = bv.x; o2[nt][3] = bv.y;
        }
        const uint2* w2H = (const uint2*)(g_wH32 + 6656);
        const uint2* w2L = (const uint2*)(g_wL32 + 6656);
#pragma unroll
        for (int kc = 0; kc < 2; kc++)
#pragma unroll
            for (int nt = 0; nt < 2; nt++) {
                uint2 h2w = __ldg(&w2H[(kc * 2 + nt) * 32 + lane]);
                uint2 l2w = __ldg(&w2L[(kc * 2 + nt) * 32 + lane]);
                mma16816(o2[nt], fh[kc], h2w.x, h2w.y);
                mma16816(o2[nt], fh[kc], l2w.x, l2w.y);
                mma16816(o2[nt], fl[kc], h2w.x, h2w.y);
            }
        float* op = out + (size_t)bt * 2048;
#pragma unroll
        for (int nt = 0; nt < 2; nt++)
#pragma unroll
            for (int rg = 0; rg < 2; rg++)
                *(float2*)(op + (size_t)(row0 + (lane >> 2) + rg * 8) * 16 +
                           nt * 8 + 2 * (lane & 3)) =
                    make_float2(o2[nt][rg * 2], o2[nt][rg * 2 + 1]);
    }
}

// ---------------------------------------------------------------------------
extern "C" void kernel_launch(void* const* d_in, const int* in_sizes, int n_in,
                              void* d_out, int out_size) {
    const float* X = (const float*)d_in[0];
    const float* A = (const float*)d_in[1];
    const float* in_w = (const float*)d_in[2];
    const float* in_b = (const float*)d_in[3];
    const float* ct_w = (const float*)d_in[4];
    const float* ct_b = (const float*)d_in[5];
    const float* cs_w = (const float*)d_in[6];
    const float* cs_b = (const float*)d_in[7];
    const float* gcn_w = (const float*)d_in[8];
    const float* gcn_b = (const float*)d_in[9];
    const float* res_w = (const float*)d_in[10];
    const float* res_b = (const float*)d_in[11];
    const float* skip_w = (const float*)d_in[12];
    const float* skip_b = (const float*)d_in[13];
    const float* out1_w = (const float*)d_in[14];
    const float* out1_b = (const float*)d_in[15];
    const float* out2_w = (const float*)d_in[16];
    const float* out2_b = (const float*)d_in[17];
    float* out = (float*)d_out;

    cudaFuncSetAttribute(k_conv_t, cudaFuncAttributeMaxDynamicSharedMemorySize,
                         K2_SMEM);
    cudaFuncSetAttribute(k_layers_f, cudaFuncAttributeMaxDynamicSharedMemorySize,
                         K3_SMEM);

    k_prep<<<128, 256>>>(A, gcn_w, skip_w, res_w, out1_w, out2_w, ct_w, cs_w);
    k_conv_t<<<1024, 512, K2_SMEM>>>(X, in_w, in_b, ct_b, cs_b);
    k_layers_f<<<4096, 256, K3_SMEM>>>(X, in_w, in_b, gcn_b, res_b, skip_b,
                                       out1_b, out2_b, out);
}